// round 1
// baseline (speedup 1.0000x reference)
#include <cuda_runtime.h>

// RoiAlign (TF crop_and_resize semantics), B=8,H=64,W=64,C=256, NB=1000, P=7.
// Output [B,NB,P,P,C] fp32. HBM-store-bound: ~401 MB out.

#define B_  8
#define H_  64
#define W_  64
#define C4_ 64      // 256 channels / 4 (float4)
#define NB_ 1000
#define P_  7
#define ITEMS_ (P_ * P_ * C4_)   // 3136 float4 per box

__global__ __launch_bounds__(256, 8)
void roi_align_kernel(const float4* __restrict__ fm,
                      const float*  __restrict__ boxes,
                      float4* __restrict__ out)
{
    const int gb = blockIdx.x;            // global box id: 0..7999
    const int b  = gb / NB_;              // batch index

    // Per-axis precompute: lo, hi, frac, valid for each of the 7 taps.
    __shared__ int   s_ylo[P_], s_yhi[P_], s_xlo[P_], s_xhi[P_];
    __shared__ float s_wy[P_],  s_wx[P_];
    __shared__ int   s_vy[P_],  s_vx[P_];

    const int tid = threadIdx.x;
    if (tid < 2 * P_) {
        const float y1 = boxes[gb * 4 + 0];
        const float x1 = boxes[gb * 4 + 1];
        const float y2 = boxes[gb * 4 + 2];
        const float x2 = boxes[gb * 4 + 3];

        const bool is_x = (tid >= P_);
        const int  t    = is_x ? (tid - P_) : tid;

        const float lo_c = is_x ? x1 : y1;
        const float hi_c = is_x ? x2 : y2;
        const float size1 = (float)(H_ - 1);   // H==W==64

        // coord = lo*(S-1) + t * (hi-lo)*(S-1)/(P-1)   (matches reference order)
        const float step  = (hi_c - lo_c) * size1 / (float)(P_ - 1);
        const float coord = lo_c * size1 + (float)t * step;

        const float lof  = floorf(coord);
        const float frac = coord - lof;
        int lo_i = (int)fminf(fmaxf(lof, 0.0f), size1);
        int hi_i = (int)fminf(fmaxf(lof + 1.0f, 0.0f), size1);
        const int valid = (coord >= 0.0f) & (coord <= size1);

        if (is_x) { s_xlo[t] = lo_i; s_xhi[t] = hi_i; s_wx[t] = frac; s_vx[t] = valid; }
        else      { s_ylo[t] = lo_i; s_yhi[t] = hi_i; s_wy[t] = frac; s_vy[t] = valid; }
    }
    __syncthreads();

    const long long out_base = (long long)gb * ITEMS_;
    const int fm_b = b * (H_ * W_);       // row-plane base in H*W units

    for (int item = tid; item < ITEMS_; item += 256) {
        const int c4 = item & (C4_ - 1);
        const int p  = item >> 6;          // 0..48
        const int py = p / P_;
        const int px = p - py * P_;

        const int   ylo = s_ylo[py], yhi = s_yhi[py];
        const int   xlo = s_xlo[px], xhi = s_xhi[px];
        const float wy  = s_wy[py],  wx  = s_wx[px];
        const int   valid = s_vy[py] & s_vx[px];

        const int r_lo = (fm_b + ylo * W_);
        const int r_hi = (fm_b + yhi * W_);

        const float4 v00 = __ldg(&fm[(r_lo + xlo) * C4_ + c4]);
        const float4 v01 = __ldg(&fm[(r_lo + xhi) * C4_ + c4]);
        const float4 v10 = __ldg(&fm[(r_hi + xlo) * C4_ + c4]);
        const float4 v11 = __ldg(&fm[(r_hi + xhi) * C4_ + c4]);

        float4 r;
        {
            // top = v00 + (v01-v00)*wx ; bot = v10 + (v11-v10)*wx ; out = top + (bot-top)*wy
            float tx, bx;
            tx = fmaf(v01.x - v00.x, wx, v00.x);
            bx = fmaf(v11.x - v10.x, wx, v10.x);
            r.x = fmaf(bx - tx, wy, tx);
            tx = fmaf(v01.y - v00.y, wx, v00.y);
            bx = fmaf(v11.y - v10.y, wx, v10.y);
            r.y = fmaf(bx - tx, wy, tx);
            tx = fmaf(v01.z - v00.z, wx, v00.z);
            bx = fmaf(v11.z - v10.z, wx, v10.z);
            r.z = fmaf(bx - tx, wy, tx);
            tx = fmaf(v01.w - v00.w, wx, v00.w);
            bx = fmaf(v11.w - v10.w, wx, v10.w);
            r.w = fmaf(bx - tx, wy, tx);
        }
        if (!valid) { r.x = 0.0f; r.y = 0.0f; r.z = 0.0f; r.w = 0.0f; }

        __stcs(&out[out_base + item], r);
    }
}

extern "C" void kernel_launch(void* const* d_in, const int* in_sizes, int n_in,
                              void* d_out, int out_size)
{
    const float4* fm    = (const float4*)d_in[0];
    const float*  boxes = (const float*)d_in[1];
    float4*       out   = (float4*)d_out;

    roi_align_kernel<<<B_ * NB_, 256>>>(fm, boxes, out);
}

// round 2
// speedup vs baseline: 1.0819x; 1.0819x over previous
#include <cuda_runtime.h>

// RoiAlign (TF crop_and_resize), B=8,H=64,W=64,C=256, NB=1000, P=7.
// L1tex-bound: 4 LDG.128 + 1 STG.128 per float4 output.
// Strategy: per-CTA precompute of all 49 pixels' corner byte-offsets +
// weights into SMEM; inner loop is pure mem + lerp.

#define B_   8
#define H_   64
#define W_   64
#define C4_  64                    // 256 ch / 4
#define NB_  1000
#define P_   7
#define NPIX (P_ * P_)             // 49
#define ITEMS_ (NPIX * C4_)        // 3136 float4 per box

__global__ __launch_bounds__(256, 6)
void roi_align_kernel(const char* __restrict__ fm,
                      const float* __restrict__ boxes,
                      char* __restrict__ out)
{
    const int gb = blockIdx.x;           // box id 0..7999
    const int b  = gb / NB_;

    // Per-pixel precomputed state: 4 corner byte offsets + (wx, wy, mask)
    __shared__ int4   s_base[NPIX];
    __shared__ float4 s_w[NPIX];

    const int tid = threadIdx.x;
    if (tid < NPIX) {
        const float y1 = __ldg(&boxes[gb * 4 + 0]);
        const float x1 = __ldg(&boxes[gb * 4 + 1]);
        const float y2 = __ldg(&boxes[gb * 4 + 2]);
        const float x2 = __ldg(&boxes[gb * 4 + 3]);

        const int py = tid / P_;
        const int px = tid - py * P_;
        const float s1 = (float)(H_ - 1);   // 63, H==W

        // coord = lo*(S-1) + t * ((hi-lo)*(S-1)/(P-1))   (reference order)
        const float ystep = (y2 - y1) * s1 / (float)(P_ - 1);
        const float xstep = (x2 - x1) * s1 / (float)(P_ - 1);
        const float yc = y1 * s1 + (float)py * ystep;
        const float xc = x1 * s1 + (float)px * xstep;

        const float ylof = floorf(yc);
        const float xlof = floorf(xc);
        const float wy = yc - ylof;
        const float wx = xc - xlof;

        const int ylo = (int)fminf(fmaxf(ylof,        0.0f), s1);
        const int yhi = (int)fminf(fmaxf(ylof + 1.0f, 0.0f), s1);
        const int xlo = (int)fminf(fmaxf(xlof,        0.0f), s1);
        const int xhi = (int)fminf(fmaxf(xlof + 1.0f, 0.0f), s1);

        const int valid = (yc >= 0.0f) & (yc <= s1) & (xc >= 0.0f) & (xc <= s1);

        // byte offset of pixel row start: ((b*H + y)*W + x) * C*4B
        const int plane = b * (H_ * W_);
        const int rlo = (plane + ylo * W_);
        const int rhi = (plane + yhi * W_);
        s_base[tid] = make_int4((rlo + xlo) << 10, (rlo + xhi) << 10,
                                (rhi + xlo) << 10, (rhi + xhi) << 10);
        s_w[tid] = make_float4(wx, wy, valid ? 1.0f : 0.0f, 0.0f);
    }
    __syncthreads();

    char* outp = out + (long long)gb * (ITEMS_ * 16);

    int item = tid;
    #pragma unroll 2
    for (int k = 0; k < 12; k++, item += 256) {
        const int p   = item >> 6;
        const int c4b = (item & (C4_ - 1)) << 4;   // channel byte offset

        const int4   bb = s_base[p];
        const float4 wv = s_w[p];

        const float4 v00 = __ldg((const float4*)(fm + bb.x + c4b));
        const float4 v01 = __ldg((const float4*)(fm + bb.y + c4b));
        const float4 v10 = __ldg((const float4*)(fm + bb.z + c4b));
        const float4 v11 = __ldg((const float4*)(fm + bb.w + c4b));

        float4 r;
        float tx, bx;
        tx = fmaf(v01.x - v00.x, wv.x, v00.x);
        bx = fmaf(v11.x - v10.x, wv.x, v10.x);
        r.x = fmaf(bx - tx, wv.y, tx) * wv.z;
        tx = fmaf(v01.y - v00.y, wv.x, v00.y);
        bx = fmaf(v11.y - v10.y, wv.x, v10.y);
        r.y = fmaf(bx - tx, wv.y, tx) * wv.z;
        tx = fmaf(v01.z - v00.z, wv.x, v00.z);
        bx = fmaf(v11.z - v10.z, wv.x, v10.z);
        r.z = fmaf(bx - tx, wv.y, tx) * wv.z;
        tx = fmaf(v01.w - v00.w, wv.x, v00.w);
        bx = fmaf(v11.w - v10.w, wv.x, v10.w);
        r.w = fmaf(bx - tx, wv.y, tx) * wv.z;

        __stcs((float4*)(outp + (item << 4)), r);
    }
    // tail: items 3072..3135 (tid < 64)
    if (item < ITEMS_) {
        const int p   = item >> 6;
        const int c4b = (item & (C4_ - 1)) << 4;

        const int4   bb = s_base[p];
        const float4 wv = s_w[p];

        const float4 v00 = __ldg((const float4*)(fm + bb.x + c4b));
        const float4 v01 = __ldg((const float4*)(fm + bb.y + c4b));
        const float4 v10 = __ldg((const float4*)(fm + bb.z + c4b));
        const float4 v11 = __ldg((const float4*)(fm + bb.w + c4b));

        float4 r;
        float tx, bx;
        tx = fmaf(v01.x - v00.x, wv.x, v00.x);
        bx = fmaf(v11.x - v10.x, wv.x, v10.x);
        r.x = fmaf(bx - tx, wv.y, tx) * wv.z;
        tx = fmaf(v01.y - v00.y, wv.x, v00.y);
        bx = fmaf(v11.y - v10.y, wv.x, v10.y);
        r.y = fmaf(bx - tx, wv.y, tx) * wv.z;
        tx = fmaf(v01.z - v00.z, wv.x, v00.z);
        bx = fmaf(v11.z - v10.z, wv.x, v10.z);
        r.z = fmaf(bx - tx, wv.y, tx) * wv.z;
        tx = fmaf(v01.w - v00.w, wv.x, v00.w);
        bx = fmaf(v11.w - v10.w, wv.x, v10.w);
        r.w = fmaf(bx - tx, wv.y, tx) * wv.z;

        __stcs((float4*)(outp + (item << 4)), r);
    }
}

extern "C" void kernel_launch(void* const* d_in, const int* in_sizes, int n_in,
                              void* d_out, int out_size)
{
    const char*  fm    = (const char*)d_in[0];
    const float* boxes = (const float*)d_in[1];
    char*        out   = (char*)d_out;

    roi_align_kernel<<<B_ * NB_, 256>>>(fm, boxes, out);
}